// round 5
// baseline (speedup 1.0000x reference)
#include <cuda_runtime.h>
#include <cuda_fp16.h>
#include <cstdint>

#define N_NODES 100000
#define F 64
#define E_MAX 2000000
#define SCAN_BLK 1024
#define NSCAN ((N_NODES + SCAN_BLK - 1) / SCAN_BLK)   // 98

// ---- scratch (allocation-free rule: __device__ globals) ----
__device__ int    g_deg[N_NODES];
__device__ int    g_off[N_NODES + 1];
__device__ int    g_cursor[N_NODES];
__device__ int    g_bsum[128];                    // padded >= NSCAN
__device__ int2   g_es[E_MAX];                    // bucketed (col, val_bits)
__device__ __half2 g_z[N_NODES * (F / 2)];        // z = x @ W, fp16, 12.8 MB

// ---------------------------------------------------------------------------
// 1. zero degree counters
// ---------------------------------------------------------------------------
__global__ void zero_deg_kernel() {
    for (int i = blockIdx.x * blockDim.x + threadIdx.x; i < N_NODES;
         i += gridDim.x * blockDim.x)
        g_deg[i] = 0;
}

// ---------------------------------------------------------------------------
// 2. histogram of edge_row
// ---------------------------------------------------------------------------
__global__ void hist_kernel(const int* __restrict__ edge_row, int n_edges) {
    for (int e = blockIdx.x * blockDim.x + threadIdx.x; e < n_edges;
         e += gridDim.x * blockDim.x)
        atomicAdd(&g_deg[edge_row[e]], 1);
}

// ---------------------------------------------------------------------------
// 3a. per-block exclusive scan of degrees; block totals to g_bsum
// ---------------------------------------------------------------------------
__global__ void scan_local_kernel() {
    __shared__ int warp_sums[32];
    const int i    = blockIdx.x * SCAN_BLK + threadIdx.x;
    const int lane = threadIdx.x & 31;
    const int wid  = threadIdx.x >> 5;

    int v = (i < N_NODES) ? g_deg[i] : 0;
    int s = v;
#pragma unroll
    for (int o = 1; o < 32; o <<= 1) {
        int t = __shfl_up_sync(0xffffffffu, s, o);
        if (lane >= o) s += t;
    }
    if (lane == 31) warp_sums[wid] = s;
    __syncthreads();
    if (wid == 0) {
        int ws = warp_sums[lane];
#pragma unroll
        for (int o = 1; o < 32; o <<= 1) {
            int t = __shfl_up_sync(0xffffffffu, ws, o);
            if (lane >= o) ws += t;
        }
        warp_sums[lane] = ws;
    }
    __syncthreads();
    const int incl = s + (wid > 0 ? warp_sums[wid - 1] : 0);
    if (i < N_NODES) g_off[i] = incl - v;                 // block-local exclusive
    if (threadIdx.x == SCAN_BLK - 1) g_bsum[blockIdx.x] = warp_sums[31];
}

// ---------------------------------------------------------------------------
// 3b. add block prefix (computed inline from g_bsum) ; init cursors ; total
// ---------------------------------------------------------------------------
__global__ void scan_add_kernel() {
    __shared__ int s_prefix;
    const int lane = threadIdx.x & 31;

    if (threadIdx.x < 32) {
        int part = 0, full = 0;
        for (int j = lane; j < NSCAN; j += 32) {
            const int b = g_bsum[j];
            full += b;
            if (j < blockIdx.x) part += b;
        }
#pragma unroll
        for (int o = 16; o > 0; o >>= 1) {
            part += __shfl_xor_sync(0xffffffffu, part, o);
            full += __shfl_xor_sync(0xffffffffu, full, o);
        }
        if (lane == 0) {
            s_prefix = part;
            if (blockIdx.x == gridDim.x - 1) g_off[N_NODES] = full;  // == n_edges
        }
    }
    __syncthreads();

    const int i = blockIdx.x * SCAN_BLK + threadIdx.x;
    if (i < N_NODES) {
        const int o = g_off[i] + s_prefix;
        g_off[i]    = o;
        g_cursor[i] = o;
    }
}

// ---------------------------------------------------------------------------
// 4. bucket edges by row
// ---------------------------------------------------------------------------
__global__ void bucket_kernel(const int*   __restrict__ edge_row,
                              const int*   __restrict__ edge_col,
                              const float* __restrict__ edge_val,
                              int n_edges) {
    for (int e = blockIdx.x * blockDim.x + threadIdx.x; e < n_edges;
         e += gridDim.x * blockDim.x) {
        const int r = edge_row[e];
        const int p = atomicAdd(&g_cursor[r], 1);
        g_es[p] = make_int2(edge_col[e], __float_as_int(edge_val[e]));
    }
}

// ---------------------------------------------------------------------------
// 5. z = x @ W  (fp16 output). One warp per row; W in smem as float2 so that
// lane L produces columns 2L, 2L+1 -> one half2 store per lane.
// ---------------------------------------------------------------------------
__global__ void zgemm_kernel(const float* __restrict__ x,
                             const float* __restrict__ weight) {
    __shared__ float2 sW2[F * 32];        // sW2[k*32 + L] = (W[k][2L], W[k][2L+1])

    for (int i = threadIdx.x; i < F * 32; i += blockDim.x)
        sW2[i] = reinterpret_cast<const float2*>(weight)[i];
    __syncthreads();

    const int lane = threadIdx.x & 31;
    const int row  = blockIdx.x * (blockDim.x >> 5) + (threadIdx.x >> 5);
    if (row >= N_NODES) return;

    const float2 s = reinterpret_cast<const float2*>(x + (size_t)row * F)[lane];

    float acc0 = 0.f, acc1 = 0.f;
#pragma unroll
    for (int k = 0; k < 32; k++) {
        const float sk0 = __shfl_sync(0xffffffffu, s.x, k);   // x[2k]
        const float sk1 = __shfl_sync(0xffffffffu, s.y, k);   // x[2k+1]
        const float2 w0 = sW2[(2 * k) * 32 + lane];
        const float2 w1 = sW2[(2 * k + 1) * 32 + lane];
        acc0 += sk0 * w0.x + sk1 * w1.x;
        acc1 += sk0 * w0.y + sk1 * w1.y;
    }

    g_z[(size_t)row * 32 + lane] = __floats2half2_rn(acc0, acc1);
}

// ---------------------------------------------------------------------------
// 6. fused pull (gather fp16 z rows) + bias + L2 normalize.
// One warp per row; lane L accumulates output columns 2L, 2L+1 in fp32.
// ---------------------------------------------------------------------------
__global__ void pull_norm_kernel(const float* __restrict__ bias,
                                 float* __restrict__ out) {
    const int lane = threadIdx.x & 31;
    const int row  = blockIdx.x * (blockDim.x >> 5) + (threadIdx.x >> 5);
    if (row >= N_NODES) return;

    const int beg = g_off[row];
    const int end = g_off[row + 1];

    float2 acc = ((const float2*)bias)[lane];   // (b[2L], b[2L+1])

    int e = beg;
    for (; e + 4 <= end; e += 4) {              // x4 unroll for gather MLP
        const int2 c0 = g_es[e + 0];
        const int2 c1 = g_es[e + 1];
        const int2 c2 = g_es[e + 2];
        const int2 c3 = g_es[e + 3];
        const float2 z0 = __half22float2(g_z[(size_t)c0.x * 32 + lane]);
        const float2 z1 = __half22float2(g_z[(size_t)c1.x * 32 + lane]);
        const float2 z2 = __half22float2(g_z[(size_t)c2.x * 32 + lane]);
        const float2 z3 = __half22float2(g_z[(size_t)c3.x * 32 + lane]);
        const float v0 = __int_as_float(c0.y), v1 = __int_as_float(c1.y);
        const float v2 = __int_as_float(c2.y), v3 = __int_as_float(c3.y);
        acc.x += v0 * z0.x + v1 * z1.x + v2 * z2.x + v3 * z3.x;
        acc.y += v0 * z0.y + v1 * z1.y + v2 * z2.y + v3 * z3.y;
    }
    for (; e < end; e++) {
        const int2 c = g_es[e];
        const float2 zv = __half22float2(g_z[(size_t)c.x * 32 + lane]);
        const float v = __int_as_float(c.y);
        acc.x += v * zv.x;
        acc.y += v * zv.y;
    }

    // row L2 normalize over the 64 outputs
    float sq = acc.x * acc.x + acc.y * acc.y;
#pragma unroll
    for (int off = 16; off > 0; off >>= 1)
        sq += __shfl_xor_sync(0xffffffffu, sq, off);
    const float inv = rsqrtf(sq);

    reinterpret_cast<float2*>(out + (size_t)row * F)[lane] =
        make_float2(acc.x * inv, acc.y * inv);
}

// ---------------------------------------------------------------------------
// Launch
// inputs: x, edge_row, edge_col, edge_val, weight, bias
// ---------------------------------------------------------------------------
extern "C" void kernel_launch(void* const* d_in, const int* in_sizes, int n_in,
                              void* d_out, int out_size) {
    const float* x        = (const float*)d_in[0];
    const int*   edge_row = (const int*)  d_in[1];
    const int*   edge_col = (const int*)  d_in[2];
    const float* edge_val = (const float*)d_in[3];
    const float* weight   = (const float*)d_in[4];
    const float* bias     = (const float*)d_in[5];
    float*       out      = (float*)d_out;

    const int n_edges = in_sizes[1];

    const int rows_per_block = 256 / 32;
    const int nblocks = (N_NODES + rows_per_block - 1) / rows_per_block;

    zero_deg_kernel<<<98, 1024>>>();
    hist_kernel<<<1184, 256>>>(edge_row, n_edges);
    scan_local_kernel<<<NSCAN, SCAN_BLK>>>();
    scan_add_kernel<<<NSCAN, SCAN_BLK>>>();
    bucket_kernel<<<1184, 256>>>(edge_row, edge_col, edge_val, n_edges);
    zgemm_kernel<<<nblocks, 256>>>(x, weight);
    pull_norm_kernel<<<nblocks, 256>>>(bias, out);
}